// round 16
// baseline (speedup 1.0000x reference)
#include <cuda_runtime.h>
#include <cstdint>

#define NN   50000
#define TT   128
#define INF  6
#define HH   32
#define NE   2000
#define NI   150000
#define RRF  16

typedef unsigned long long u64;

// ---------------- scratch (device globals, no allocation) ----------------
__device__ float g_A  [NN * HH];
__device__ float g_XW [NN * HH];
__device__ float g_AGG[NN * HH];
__device__ float g_EF [NE * HH];
__device__ float g_degB[NE];
__device__ float g_degD[NN];

// ---------------- helpers ----------------
__device__ __forceinline__ u64 ffma2(u64 a, u64 b, u64 c) {
    u64 d;
    asm("fma.rn.f32x2 %0, %1, %2, %3;" : "=l"(d) : "l"(a), "l"(b), "l"(c));
    return d;
}
__device__ __forceinline__ u64 pk2(float lo, float hi) {
    u64 r;
    asm("mov.b64 %0, {%1, %2};" : "=l"(r) : "f"(lo), "f"(hi));
    return r;
}
__device__ __forceinline__ float2 up2(u64 v) {
    float2 f;
    asm("mov.b64 {%0, %1}, %2;" : "=f"(f.x), "=f"(f.y) : "l"(v));
    return f;
}
__device__ __forceinline__ float tanh_fast(float x) {
    float t;
    asm("tanh.approx.f32 %0, %1;" : "=f"(t) : "f"(x));
    return t;
}
__device__ __forceinline__ float sigm(float x) {
    float t;
    asm("tanh.approx.f32 %0, %1;" : "=f"(t) : "f"(0.5f * x));
    return fmaf(t, 0.5f, 0.5f);
}

// ---------------- GRU: warp GEMV, weights in regs, h via smem broadcast ----
// Lane j holds weight rows j/32+j/64+j (r,z,n) in registers (K-paired u64).
// h exchange: double-buffered smem, LDS.128 broadcast (r15 win).
// NEW (r16): x(t+1) prefetched into registers during step t — the x LDG was
// consumed ~20 instr after issue, exposing L2-class latency every time a
// 128B line boundary was crossed; now it has the whole hh-FFMA block to land.
__global__ void __launch_bounds__(32, 11) gru_warp_kernel(
    const float* __restrict__ x,   // [NN][TT][INF]
    const float* __restrict__ W_ih, const float* __restrict__ W_hh,
    const float* __restrict__ b_ih, const float* __restrict__ b_hh)
{
    __shared__ __align__(16) float hbuf[2][2][32];   // [buffer][node][j]
    const int j = threadIdx.x;     // lane = output index

    // ---- persistent per-lane weights ----
    u64 wr2[16], wz2[16], wn2[16];
#pragma unroll
    for (int k2 = 0; k2 < 16; k2++) {
        wr2[k2] = pk2(W_hh[      j * HH + 2 * k2], W_hh[      j * HH + 2 * k2 + 1]);
        wz2[k2] = pk2(W_hh[(32 + j) * HH + 2 * k2], W_hh[(32 + j) * HH + 2 * k2 + 1]);
        wn2[k2] = pk2(W_hh[(64 + j) * HH + 2 * k2], W_hh[(64 + j) * HH + 2 * k2 + 1]);
    }
    float ur[6], uz[6], un[6];
#pragma unroll
    for (int f = 0; f < 6; f++) {
        ur[f] = W_ih[      j * INF + f];
        uz[f] = W_ih[(32 + j) * INF + f];
        un[f] = W_ih[(64 + j) * INF + f];
    }
    const float brj  = b_ih[j]      + b_hh[j];
    const float bzj  = b_ih[32 + j] + b_hh[32 + j];
    const float bhnj = b_hh[64 + j];
    const float binj = b_ih[64 + j];

    for (int pair = blockIdx.x; pair < NN / 2; pair += gridDim.x) {
        const int nodeA = pair * 2;
        const float* xA = x + (size_t)nodeA * (TT * INF);
        const float* xB = xA + TT * INF;

        float hAj = 0.f, hBj = 0.f;
        hbuf[0][0][j] = 0.f;
        hbuf[0][1][j] = 0.f;
        __syncwarp();

        // preload x for t=0
        float xa[6], xb[6];
        {
            float2 p0 = *(const float2*)(xA);
            float2 p1 = *(const float2*)(xA + 2);
            float2 p2 = *(const float2*)(xA + 4);
            xa[0] = p0.x; xa[1] = p0.y; xa[2] = p1.x; xa[3] = p1.y; xa[4] = p2.x; xa[5] = p2.y;
            float2 q0 = *(const float2*)(xB);
            float2 q1 = *(const float2*)(xB + 2);
            float2 q2 = *(const float2*)(xB + 4);
            xb[0] = q0.x; xb[1] = q0.y; xb[2] = q1.x; xb[3] = q1.y; xb[4] = q2.x; xb[5] = q2.y;
        }

        for (int t = 0; t < TT; t++) {
            const int rb = t & 1;       // read buffer (written end of t-1)
            const int wb = rb ^ 1;

            // ---- prefetch x(t+1) — lands during the hh block below ----
            float xan[6], xbn[6];
            if (t < TT - 1) {
                const float* pA = xA + (t + 1) * 6;
                const float* pB = xB + (t + 1) * 6;
                float2 p0 = *(const float2*)(pA);
                float2 p1 = *(const float2*)(pA + 2);
                float2 p2 = *(const float2*)(pA + 4);
                xan[0] = p0.x; xan[1] = p0.y; xan[2] = p1.x;
                xan[3] = p1.y; xan[4] = p2.x; xan[5] = p2.y;
                float2 q0 = *(const float2*)(pB);
                float2 q1 = *(const float2*)(pB + 2);
                float2 q2 = *(const float2*)(pB + 4);
                xbn[0] = q0.x; xbn[1] = q0.y; xbn[2] = q1.x;
                xbn[3] = q1.y; xbn[4] = q2.x; xbn[5] = q2.y;
            }

            // ---- ih projections (biases folded) ----
            float ihrA = brj, ihzA = bzj, ihnA = binj;
            float ihrB = brj, ihzB = bzj, ihnB = binj;
#pragma unroll
            for (int f = 0; f < 6; f++) {
                ihrA = fmaf(ur[f], xa[f], ihrA);
                ihzA = fmaf(uz[f], xa[f], ihzA);
                ihnA = fmaf(un[f], xa[f], ihnA);
                ihrB = fmaf(ur[f], xb[f], ihrB);
                ihzB = fmaf(uz[f], xb[f], ihzB);
                ihnB = fmaf(un[f], xb[f], ihnB);
            }

            // ---- hh dot products: h pairs via LDS.128 broadcast ----
            u64 aR = 0, aZ = 0, aN = 0, bR = 0, bZ = 0, bN = 0;
#pragma unroll
            for (int i = 0; i < 8; i++) {
                ulonglong2 pa = *reinterpret_cast<const ulonglong2*>(&hbuf[rb][0][4 * i]);
                ulonglong2 pb = *reinterpret_cast<const ulonglong2*>(&hbuf[rb][1][4 * i]);
                aR = ffma2(wr2[2 * i],     pa.x, aR);
                aR = ffma2(wr2[2 * i + 1], pa.y, aR);
                bR = ffma2(wr2[2 * i],     pb.x, bR);
                bR = ffma2(wr2[2 * i + 1], pb.y, bR);
                aZ = ffma2(wz2[2 * i],     pa.x, aZ);
                aZ = ffma2(wz2[2 * i + 1], pa.y, aZ);
                bZ = ffma2(wz2[2 * i],     pb.x, bZ);
                bZ = ffma2(wz2[2 * i + 1], pb.y, bZ);
                aN = ffma2(wn2[2 * i],     pa.x, aN);
                aN = ffma2(wn2[2 * i + 1], pa.y, aN);
                bN = ffma2(wn2[2 * i],     pb.x, bN);
                bN = ffma2(wn2[2 * i + 1], pb.y, bN);
            }

            // ---- horizontal add + gates + update ----
            float2 v;
            v = up2(aR); float rA = sigm(v.x + v.y + ihrA);
            v = up2(aZ); float zA = sigm(v.x + v.y + ihzA);
            v = up2(aN); float nA = tanh_fast(fmaf(rA, v.x + v.y + bhnj, ihnA));
            hAj = nA + zA * (hAj - nA);

            v = up2(bR); float rB = sigm(v.x + v.y + ihrB);
            v = up2(bZ); float zB = sigm(v.x + v.y + ihzB);
            v = up2(bN); float nB = tanh_fast(fmaf(rB, v.x + v.y + bhnj, ihnB));
            hBj = nB + zB * (hBj - nB);

            // ---- publish h for next step (double buffer, 1 syncwarp) ----
            hbuf[wb][0][j] = hAj;
            hbuf[wb][1][j] = hBj;
            __syncwarp();

#pragma unroll
            for (int f = 0; f < 6; f++) { xa[f] = xan[f]; xb[f] = xbn[f]; }
        }

        float vA = hAj, vB = hBj;
        g_A[(size_t)nodeA * HH + j]       = vA > 0.f ? vA : 0.01f * vA;
        g_A[(size_t)(nodeA + 1) * HH + j] = vB > 0.f ? vB : 0.01f * vB;
        __syncwarp();   // all reads of hbuf done before next pair re-inits
    }
}

// ---------------- hypergraph kernels ----------------
__device__ __forceinline__ void red_add_v2(float* p, float a, float b) {
    asm volatile("red.global.add.v2.f32 [%0], {%1, %2};"
                 :: "l"(p), "f"(a), "f"(b) : "memory");
}
__global__ void zero_deg_kernel() {
    int i = blockIdx.x * blockDim.x + threadIdx.x;
    if (i < NE) g_degB[i] = 0.f;
    if (i < NN) g_degD[i] = 0.f;
}
__global__ void count_deg_kernel(const int* __restrict__ nidx, const int* __restrict__ eidx) {
    int i = blockIdx.x * blockDim.x + threadIdx.x;
    if (i < NI) {
        atomicAdd(&g_degB[eidx[i]], 1.f);
        atomicAdd(&g_degD[nidx[i]], 1.f);
    }
}
__global__ void invert_deg_kernel() {
    int i = blockIdx.x * blockDim.x + threadIdx.x;
    if (i < NE) { float v = g_degB[i]; g_degB[i] = v > 0.f ? 1.f / v : 0.f; }
    if (i < NN) { float v = g_degD[i]; g_degD[i] = v > 0.f ? 1.f / v : 0.f; }
}
__global__ void zero_ef_agg_kernel() {
    int i = blockIdx.x * blockDim.x + threadIdx.x;
    if (i < NE * HH) g_EF[i] = 0.f;
    if (i < NN * HH) g_AGG[i] = 0.f;
}
__global__ void scatter_edge_kernel(const int* __restrict__ nidx, const int* __restrict__ eidx) {
    int idx = blockIdx.x * blockDim.x + threadIdx.x;
    if (idx < NI * 16) {
        int i = idx >> 4, c = (idx & 15) * 2;
        const float2 v = *reinterpret_cast<const float2*>(&g_XW[(size_t)nidx[i] * HH + c]);
        red_add_v2(&g_EF[eidx[i] * HH + c], v.x, v.y);
    }
}
__global__ void scatter_node_kernel(const int* __restrict__ nidx, const int* __restrict__ eidx) {
    int idx = blockIdx.x * blockDim.x + threadIdx.x;
    if (idx < NI * 16) {
        int i = idx >> 4, c = (idx & 15) * 2;
        int e = eidx[i];
        float s = g_degB[e];
        const float2 v = *reinterpret_cast<const float2*>(&g_EF[e * HH + c]);
        red_add_v2(&g_AGG[(size_t)nidx[i] * HH + c], v.x * s, v.y * s);
    }
}
__global__ void finalize_kernel(const float* __restrict__ bias) {
    int idx = blockIdx.x * blockDim.x + threadIdx.x;
    if (idx < NN * HH) {
        int n = idx >> 5, c = idx & 31;
        float v = g_AGG[idx] * g_degD[n] + bias[c];
        g_A[idx] = v > 0.f ? v : 0.2f * v;
    }
}
__global__ void dense_kernel(const float* __restrict__ W, const float* __restrict__ bias,
                             float* __restrict__ extout,
                             int nout, int hasBias, int hasAct, float slope) {
    __shared__ float sW[32 * 32];
    for (int i = threadIdx.x; i < nout * 32; i += blockDim.x) sW[i] = W[i];
    __syncthreads();
    int n = blockIdx.x * blockDim.x + threadIdx.x;
    if (n >= NN) return;
    float xin[32];
#pragma unroll
    for (int k = 0; k < 32; k++) xin[k] = g_A[(size_t)n * 32 + k];
    float* o = extout ? extout : g_XW;
    for (int j = 0; j < nout; j++) {
        float acc = hasBias ? bias[j] : 0.f;
#pragma unroll
        for (int k = 0; k < 32; k++) acc = fmaf(xin[k], sW[j * 32 + k], acc);
        if (hasAct) acc = acc > 0.f ? acc : slope * acc;
        o[(size_t)n * nout + j] = acc;
    }
}

// ---------------- launch ----------------
// gru_warp_kernel stays the 4th launch (the slot the profiler captures).
extern "C" void kernel_launch(void* const* d_in, const int* in_sizes, int n_in,
                              void* d_out, int out_size) {
    const float* price = (const float*)d_in[0];
    const float* W_ih = (const float*)d_in[2];
    const float* W_hh = (const float*)d_in[3];
    const float* b_ih = (const float*)d_in[4];
    const float* b_hh = (const float*)d_in[5];
    const float* W1   = (const float*)d_in[6];
    const float* b1   = (const float*)d_in[7];
    const float* W2   = (const float*)d_in[8];
    const float* b2   = (const float*)d_in[9];
    const float* Wl   = (const float*)d_in[10];
    const float* bl   = (const float*)d_in[11];
    const int*   nidx = (const int*)d_in[12];
    const int*   eidx = (const int*)d_in[13];
    float* out = (float*)d_out;

    const int B256 = 256;
    zero_deg_kernel<<<(NN + B256 - 1) / B256, B256>>>();                  // 1
    count_deg_kernel<<<(NI + B256 - 1) / B256, B256>>>(nidx, eidx);       // 2
    invert_deg_kernel<<<(NN + B256 - 1) / B256, B256>>>();                // 3
    gru_warp_kernel<<<1628, 32>>>(price, W_ih, W_hh, b_ih, b_hh);         // 4 <- profiled

    // conv1
    dense_kernel<<<(NN + 127) / 128, 128>>>(W1, nullptr, nullptr, 32, 0, 0, 0.f);
    zero_ef_agg_kernel<<<(NN * HH + B256 - 1) / B256, B256>>>();
    scatter_edge_kernel<<<(NI * 16 + B256 - 1) / B256, B256>>>(nidx, eidx);
    scatter_node_kernel<<<(NI * 16 + B256 - 1) / B256, B256>>>(nidx, eidx);
    finalize_kernel<<<(NN * HH + B256 - 1) / B256, B256>>>(b1);

    // conv2
    dense_kernel<<<(NN + 127) / 128, 128>>>(W2, nullptr, nullptr, 32, 0, 0, 0.f);
    zero_ef_agg_kernel<<<(NN * HH + B256 - 1) / B256, B256>>>();
    scatter_edge_kernel<<<(NI * 16 + B256 - 1) / B256, B256>>>(nidx, eidx);
    scatter_node_kernel<<<(NI * 16 + B256 - 1) / B256, B256>>>(nidx, eidx);
    finalize_kernel<<<(NN * HH + B256 - 1) / B256, B256>>>(b2);

    dense_kernel<<<(NN + 127) / 128, 128>>>(Wl, bl, out, RRF, 1, 1, 0.01f);
}

// round 17
// speedup vs baseline: 1.1694x; 1.1694x over previous
#include <cuda_runtime.h>
#include <cstdint>

#define NN   50000
#define TT   128
#define INF  6
#define HH   32
#define NE   2000
#define NI   150000
#define RRF  16

typedef unsigned long long u64;

// ---------------- scratch (device globals, no allocation) ----------------
__device__ float g_A  [NN * HH];
__device__ float g_XW [NN * HH];
__device__ float g_AGG[NN * HH];
__device__ float g_EF [NE * HH];
__device__ float g_degB[NE];
__device__ float g_degD[NN];

// ---------------- helpers ----------------
__device__ __forceinline__ u64 ffma2(u64 a, u64 b, u64 c) {
    u64 d;
    asm("fma.rn.f32x2 %0, %1, %2, %3;" : "=l"(d) : "l"(a), "l"(b), "l"(c));
    return d;
}
__device__ __forceinline__ u64 pk2(float lo, float hi) {
    u64 r;
    asm("mov.b64 %0, {%1, %2};" : "=l"(r) : "f"(lo), "f"(hi));
    return r;
}
__device__ __forceinline__ float2 up2(u64 v) {
    float2 f;
    asm("mov.b64 {%0, %1}, %2;" : "=f"(f.x), "=f"(f.y) : "l"(v));
    return f;
}
__device__ __forceinline__ float tanh_fast(float x) {
    float t;
    asm("tanh.approx.f32 %0, %1;" : "=f"(t) : "f"(x));
    return t;
}
__device__ __forceinline__ float sigm(float x) {
    float t;
    asm("tanh.approx.f32 %0, %1;" : "=f"(t) : "f"(0.5f * x));
    return fmaf(t, 0.5f, 0.5f);
}

// ---------------- GRU: warp GEMV, weights in regs, h via smem broadcast ----
// Lane j holds weight rows j/32+j/64+j (r,z,n) in registers (K-paired u64).
// h exchange: double-buffered smem, LDS.128 broadcast (r15 layout, which is
// the best measured: r16's x-prefetch regressed — the x loads were already
// covered; its 12 extra MOVs/step cost more than the latency they hid).
// r17 change: (32,11) -> (32,12). regs=166 <= cap 170, so the same
// allocation packs 12 blocks/SM: +9% warps for a latency-bound kernel.
__global__ void __launch_bounds__(32, 12) gru_warp_kernel(
    const float* __restrict__ x,   // [NN][TT][INF]
    const float* __restrict__ W_ih, const float* __restrict__ W_hh,
    const float* __restrict__ b_ih, const float* __restrict__ b_hh)
{
    __shared__ __align__(16) float hbuf[2][2][32];   // [buffer][node][j]
    const int j = threadIdx.x;     // lane = output index

    // ---- persistent per-lane weights ----
    u64 wr2[16], wz2[16], wn2[16];
#pragma unroll
    for (int k2 = 0; k2 < 16; k2++) {
        wr2[k2] = pk2(W_hh[      j * HH + 2 * k2], W_hh[      j * HH + 2 * k2 + 1]);
        wz2[k2] = pk2(W_hh[(32 + j) * HH + 2 * k2], W_hh[(32 + j) * HH + 2 * k2 + 1]);
        wn2[k2] = pk2(W_hh[(64 + j) * HH + 2 * k2], W_hh[(64 + j) * HH + 2 * k2 + 1]);
    }
    float ur[6], uz[6], un[6];
#pragma unroll
    for (int f = 0; f < 6; f++) {
        ur[f] = W_ih[      j * INF + f];
        uz[f] = W_ih[(32 + j) * INF + f];
        un[f] = W_ih[(64 + j) * INF + f];
    }
    const float brj  = b_ih[j]      + b_hh[j];
    const float bzj  = b_ih[32 + j] + b_hh[32 + j];
    const float bhnj = b_hh[64 + j];
    const float binj = b_ih[64 + j];

    for (int pair = blockIdx.x; pair < NN / 2; pair += gridDim.x) {
        const int nodeA = pair * 2;
        const float* xA = x + (size_t)nodeA * (TT * INF);
        const float* xB = xA + TT * INF;

        float hAj = 0.f, hBj = 0.f;
        hbuf[0][0][j] = 0.f;
        hbuf[0][1][j] = 0.f;
        __syncwarp();

        for (int t = 0; t < TT; t++) {
            const int rb = t & 1;       // read buffer (written end of t-1)
            const int wb = rb ^ 1;

            // ---- ih projections (uniform loads, biases folded) ----
            float2 a01 = *(const float2*)(xA + t * 6);
            float2 a23 = *(const float2*)(xA + t * 6 + 2);
            float2 a45 = *(const float2*)(xA + t * 6 + 4);
            float2 b01 = *(const float2*)(xB + t * 6);
            float2 b23 = *(const float2*)(xB + t * 6 + 2);
            float2 b45 = *(const float2*)(xB + t * 6 + 4);
            float xa[6] = {a01.x, a01.y, a23.x, a23.y, a45.x, a45.y};
            float xb[6] = {b01.x, b01.y, b23.x, b23.y, b45.x, b45.y};

            float ihrA = brj, ihzA = bzj, ihnA = binj;
            float ihrB = brj, ihzB = bzj, ihnB = binj;
#pragma unroll
            for (int f = 0; f < 6; f++) {
                ihrA = fmaf(ur[f], xa[f], ihrA);
                ihzA = fmaf(uz[f], xa[f], ihzA);
                ihnA = fmaf(un[f], xa[f], ihnA);
                ihrB = fmaf(ur[f], xb[f], ihrB);
                ihzB = fmaf(uz[f], xb[f], ihzB);
                ihnB = fmaf(un[f], xb[f], ihnB);
            }

            // ---- hh dot products: h pairs via LDS.128 broadcast ----
            u64 aR = 0, aZ = 0, aN = 0, bR = 0, bZ = 0, bN = 0;
#pragma unroll
            for (int i = 0; i < 8; i++) {
                ulonglong2 pa = *reinterpret_cast<const ulonglong2*>(&hbuf[rb][0][4 * i]);
                ulonglong2 pb = *reinterpret_cast<const ulonglong2*>(&hbuf[rb][1][4 * i]);
                aR = ffma2(wr2[2 * i],     pa.x, aR);
                aR = ffma2(wr2[2 * i + 1], pa.y, aR);
                bR = ffma2(wr2[2 * i],     pb.x, bR);
                bR = ffma2(wr2[2 * i + 1], pb.y, bR);
                aZ = ffma2(wz2[2 * i],     pa.x, aZ);
                aZ = ffma2(wz2[2 * i + 1], pa.y, aZ);
                bZ = ffma2(wz2[2 * i],     pb.x, bZ);
                bZ = ffma2(wz2[2 * i + 1], pb.y, bZ);
                aN = ffma2(wn2[2 * i],     pa.x, aN);
                aN = ffma2(wn2[2 * i + 1], pa.y, aN);
                bN = ffma2(wn2[2 * i],     pb.x, bN);
                bN = ffma2(wn2[2 * i + 1], pb.y, bN);
            }

            // ---- horizontal add + gates + update ----
            float2 v;
            v = up2(aR); float rA = sigm(v.x + v.y + ihrA);
            v = up2(aZ); float zA = sigm(v.x + v.y + ihzA);
            v = up2(aN); float nA = tanh_fast(fmaf(rA, v.x + v.y + bhnj, ihnA));
            hAj = nA + zA * (hAj - nA);

            v = up2(bR); float rB = sigm(v.x + v.y + ihrB);
            v = up2(bZ); float zB = sigm(v.x + v.y + ihzB);
            v = up2(bN); float nB = tanh_fast(fmaf(rB, v.x + v.y + bhnj, ihnB));
            hBj = nB + zB * (hBj - nB);

            // ---- publish h for next step (double buffer, 1 syncwarp) ----
            hbuf[wb][0][j] = hAj;
            hbuf[wb][1][j] = hBj;
            __syncwarp();
        }

        float vA = hAj, vB = hBj;
        g_A[(size_t)nodeA * HH + j]       = vA > 0.f ? vA : 0.01f * vA;
        g_A[(size_t)(nodeA + 1) * HH + j] = vB > 0.f ? vB : 0.01f * vB;
        __syncwarp();   // all reads of hbuf done before next pair re-inits
    }
}

// ---------------- hypergraph kernels ----------------
__device__ __forceinline__ void red_add_v2(float* p, float a, float b) {
    asm volatile("red.global.add.v2.f32 [%0], {%1, %2};"
                 :: "l"(p), "f"(a), "f"(b) : "memory");
}
__global__ void zero_deg_kernel() {
    int i = blockIdx.x * blockDim.x + threadIdx.x;
    if (i < NE) g_degB[i] = 0.f;
    if (i < NN) g_degD[i] = 0.f;
}
__global__ void count_deg_kernel(const int* __restrict__ nidx, const int* __restrict__ eidx) {
    int i = blockIdx.x * blockDim.x + threadIdx.x;
    if (i < NI) {
        atomicAdd(&g_degB[eidx[i]], 1.f);
        atomicAdd(&g_degD[nidx[i]], 1.f);
    }
}
__global__ void invert_deg_kernel() {
    int i = blockIdx.x * blockDim.x + threadIdx.x;
    if (i < NE) { float v = g_degB[i]; g_degB[i] = v > 0.f ? 1.f / v : 0.f; }
    if (i < NN) { float v = g_degD[i]; g_degD[i] = v > 0.f ? 1.f / v : 0.f; }
}
__global__ void zero_ef_agg_kernel() {
    int i = blockIdx.x * blockDim.x + threadIdx.x;
    if (i < NE * HH) g_EF[i] = 0.f;
    if (i < NN * HH) g_AGG[i] = 0.f;
}
__global__ void scatter_edge_kernel(const int* __restrict__ nidx, const int* __restrict__ eidx) {
    int idx = blockIdx.x * blockDim.x + threadIdx.x;
    if (idx < NI * 16) {
        int i = idx >> 4, c = (idx & 15) * 2;
        const float2 v = *reinterpret_cast<const float2*>(&g_XW[(size_t)nidx[i] * HH + c]);
        red_add_v2(&g_EF[eidx[i] * HH + c], v.x, v.y);
    }
}
__global__ void scatter_node_kernel(const int* __restrict__ nidx, const int* __restrict__ eidx) {
    int idx = blockIdx.x * blockDim.x + threadIdx.x;
    if (idx < NI * 16) {
        int i = idx >> 4, c = (idx & 15) * 2;
        int e = eidx[i];
        float s = g_degB[e];
        const float2 v = *reinterpret_cast<const float2*>(&g_EF[e * HH + c]);
        red_add_v2(&g_AGG[(size_t)nidx[i] * HH + c], v.x * s, v.y * s);
    }
}
__global__ void finalize_kernel(const float* __restrict__ bias) {
    int idx = blockIdx.x * blockDim.x + threadIdx.x;
    if (idx < NN * HH) {
        int n = idx >> 5, c = idx & 31;
        float v = g_AGG[idx] * g_degD[n] + bias[c];
        g_A[idx] = v > 0.f ? v : 0.2f * v;
    }
}
__global__ void dense_kernel(const float* __restrict__ W, const float* __restrict__ bias,
                             float* __restrict__ extout,
                             int nout, int hasBias, int hasAct, float slope) {
    __shared__ float sW[32 * 32];
    for (int i = threadIdx.x; i < nout * 32; i += blockDim.x) sW[i] = W[i];
    __syncthreads();
    int n = blockIdx.x * blockDim.x + threadIdx.x;
    if (n >= NN) return;
    float xin[32];
#pragma unroll
    for (int k = 0; k < 32; k++) xin[k] = g_A[(size_t)n * 32 + k];
    float* o = extout ? extout : g_XW;
    for (int j = 0; j < nout; j++) {
        float acc = hasBias ? bias[j] : 0.f;
#pragma unroll
        for (int k = 0; k < 32; k++) acc = fmaf(xin[k], sW[j * 32 + k], acc);
        if (hasAct) acc = acc > 0.f ? acc : slope * acc;
        o[(size_t)n * nout + j] = acc;
    }
}

// ---------------- launch ----------------
// gru_warp_kernel stays the 4th launch (the slot the profiler captures).
extern "C" void kernel_launch(void* const* d_in, const int* in_sizes, int n_in,
                              void* d_out, int out_size) {
    const float* price = (const float*)d_in[0];
    const float* W_ih = (const float*)d_in[2];
    const float* W_hh = (const float*)d_in[3];
    const float* b_ih = (const float*)d_in[4];
    const float* b_hh = (const float*)d_in[5];
    const float* W1   = (const float*)d_in[6];
    const float* b1   = (const float*)d_in[7];
    const float* W2   = (const float*)d_in[8];
    const float* b2   = (const float*)d_in[9];
    const float* Wl   = (const float*)d_in[10];
    const float* bl   = (const float*)d_in[11];
    const int*   nidx = (const int*)d_in[12];
    const int*   eidx = (const int*)d_in[13];
    float* out = (float*)d_out;

    const int B256 = 256;
    zero_deg_kernel<<<(NN + B256 - 1) / B256, B256>>>();                  // 1
    count_deg_kernel<<<(NI + B256 - 1) / B256, B256>>>(nidx, eidx);       // 2
    invert_deg_kernel<<<(NN + B256 - 1) / B256, B256>>>();                // 3
    gru_warp_kernel<<<1776, 32>>>(price, W_ih, W_hh, b_ih, b_hh);         // 4 <- profiled

    // conv1
    dense_kernel<<<(NN + 127) / 128, 128>>>(W1, nullptr, nullptr, 32, 0, 0, 0.f);
    zero_ef_agg_kernel<<<(NN * HH + B256 - 1) / B256, B256>>>();
    scatter_edge_kernel<<<(NI * 16 + B256 - 1) / B256, B256>>>(nidx, eidx);
    scatter_node_kernel<<<(NI * 16 + B256 - 1) / B256, B256>>>(nidx, eidx);
    finalize_kernel<<<(NN * HH + B256 - 1) / B256, B256>>>(b1);

    // conv2
    dense_kernel<<<(NN + 127) / 128, 128>>>(W2, nullptr, nullptr, 32, 0, 0, 0.f);
    zero_ef_agg_kernel<<<(NN * HH + B256 - 1) / B256, B256>>>();
    scatter_edge_kernel<<<(NI * 16 + B256 - 1) / B256, B256>>>(nidx, eidx);
    scatter_node_kernel<<<(NI * 16 + B256 - 1) / B256, B256>>>(nidx, eidx);
    finalize_kernel<<<(NN * HH + B256 - 1) / B256, B256>>>(b2);

    dense_kernel<<<(NN + 127) / 128, 128>>>(Wl, bl, out, RRF, 1, 1, 0.01f);
}